// round 2
// baseline (speedup 1.0000x reference)
#include <cuda_runtime.h>
#include <math.h>

#define B_    256
#define T_    64
#define H_    256
#define D_    512
#define N3_   768
#define NCTA  128
#define NTHR  256
#define SSUB  4

// ---------------- device scratch (no allocations allowed) -------------------
__device__ __align__(16) float g_W1T[H_ * D_];        // W1 transposed: [h][d]
__device__ __align__(16) float g_Wc [H_ * H_];        // fused weight:  [j][h]
__device__ __align__(16) float g_bc [H_];             // fused bias
__device__ __align__(16) float g_u  [B_ * H_];        // current f input
__device__ __align__(16) float g_y  [B_ * H_];        // ODE state
__device__ __align__(16) float g_acc[B_ * H_];        // RK4 accumulator
__device__ __align__(16) float g_part [8 * B_ * H_];  // GEMM partial slabs (ODE & Wc)
__device__ __align__(16) float g_partG[2 * B_ * N3_]; // GRU GEMM partial slabs

__device__ unsigned g_arrive  = 0;
__device__ unsigned g_release = 0;

// ---------------- grid barrier (replay-safe: monotone release) --------------
__device__ __forceinline__ void gbar(unsigned &next) {
    __threadfence();          // my stores -> L2
    __syncthreads();          // whole CTA done
    if (threadIdx.x == 0) {
        unsigned tgt = next;
        if (atomicAdd(&g_arrive, 1u) == NCTA - 1) {
            g_arrive = 0;
            __threadfence();
            *(volatile unsigned*)&g_release = tgt;
        } else {
            while ((int)(*(volatile unsigned*)&g_release - tgt) < 0) { }
        }
        __threadfence();
    }
    __syncthreads();
    next++;
}

// ---------------- GEMM: C_partial[ks][m][n] = sum_{k in chunk} A[m][k]*W[n][k]
// 64x64 tiles, 4x4 per thread, k-major smem (stride 68, conflict-free).
__device__ void gemm64(const float* A, int lda, const float* W, int ldw,
                       float* part, int Ncols, int slabStride,
                       int Mt, int Nt, int Ks, int Kc,
                       float* sA, float* sW)
{
    const int ntasks = Mt * Nt * Ks;
    const int tr = threadIdx.x >> 4;    // 0..15
    const int tc = threadIdx.x & 15;    // 0..15

    for (int task = blockIdx.x; task < ntasks; task += NCTA) {
        const int ks  = task / (Mt * Nt);
        const int rem = task - ks * (Mt * Nt);
        const int mt  = rem / Nt;
        const int nt  = rem - mt * Nt;
        const int m0 = mt << 6, n0 = nt << 6, k0 = ks * Kc;

        float acc[4][4];
        #pragma unroll
        for (int i = 0; i < 4; i++)
            #pragma unroll
            for (int j = 0; j < 4; j++) acc[i][j] = 0.f;

        for (int kc = 0; kc < Kc; kc += 32) {
            const int kb = k0 + kc;
            __syncthreads();   // previous chunk's reads complete
            #pragma unroll
            for (int rpt = 0; rpt < 2; rpt++) {
                int idx = threadIdx.x + rpt * 256;   // 0..511
                int m  = idx >> 3;                   // 0..63
                int kq = (idx & 7) << 2;             // 0,4,...,28
                float4 va = __ldcg((const float4*)(A + (size_t)(m0 + m) * lda + kb + kq));
                sA[(kq + 0) * 68 + m] = va.x;
                sA[(kq + 1) * 68 + m] = va.y;
                sA[(kq + 2) * 68 + m] = va.z;
                sA[(kq + 3) * 68 + m] = va.w;
                float4 vw = __ldcg((const float4*)(W + (size_t)(n0 + m) * ldw + kb + kq));
                sW[(kq + 0) * 68 + m] = vw.x;
                sW[(kq + 1) * 68 + m] = vw.y;
                sW[(kq + 2) * 68 + m] = vw.z;
                sW[(kq + 3) * 68 + m] = vw.w;
            }
            __syncthreads();

            const float* pa = sA + tr * 4;
            const float* pw = sW + tc * 4;
            #pragma unroll
            for (int kk = 0; kk < 32; kk++) {
                float4 a = *(const float4*)(pa + kk * 68);
                float4 w = *(const float4*)(pw + kk * 68);
                acc[0][0] += a.x * w.x; acc[0][1] += a.x * w.y;
                acc[0][2] += a.x * w.z; acc[0][3] += a.x * w.w;
                acc[1][0] += a.y * w.x; acc[1][1] += a.y * w.y;
                acc[1][2] += a.y * w.z; acc[1][3] += a.y * w.w;
                acc[2][0] += a.z * w.x; acc[2][1] += a.z * w.y;
                acc[2][2] += a.z * w.z; acc[2][3] += a.z * w.w;
                acc[3][0] += a.w * w.x; acc[3][1] += a.w * w.y;
                acc[3][2] += a.w * w.z; acc[3][3] += a.w * w.w;
            }
        }

        float* p = part + (size_t)ks * slabStride
                        + (size_t)(m0 + tr * 4) * Ncols + n0 + tc * 4;
        #pragma unroll
        for (int i = 0; i < 4; i++) {
            float4 v = make_float4(acc[i][0], acc[i][1], acc[i][2], acc[i][3]);
            *(float4*)(p + (size_t)i * Ncols) = v;
        }
    }
}

__device__ __forceinline__ float sigm(float x) { return 1.f / (1.f + expf(-x)); }

// ---------------- persistent kernel ------------------------------------------
__global__ void __launch_bounds__(NTHR, 1)
ode_rnn_kernel(const float* __restrict__ batch, const float* __restrict__ mask,
               const float* __restrict__ W1,   const float* __restrict__ b1,
               const float* __restrict__ W2,   const float* __restrict__ b2,
               const float* __restrict__ W_ih, const float* __restrict__ b_ih,
               const float* __restrict__ W_hh, const float* __restrict__ b_hh,
               float* __restrict__ out)
{
    __shared__ __align__(16) float sA[32 * 68];
    __shared__ __align__(16) float sW[32 * 68];
    __shared__ unsigned s_base;

    const int tid  = threadIdx.x;
    const int gtid = blockIdx.x * NTHR + tid;
    const int GSTR = NCTA * NTHR;   // 32768

    if (tid == 0) s_base = *(volatile unsigned*)&g_release;
    __syncthreads();
    unsigned bar = s_base + 1;

    // ---- P0: init state, transpose W1, compute bc ----
    for (int e = gtid; e < B_ * H_; e += GSTR) { g_y[e] = 0.f; g_u[e] = 0.f; }
    for (int e = gtid; e < H_ * D_; e += GSTR) {
        int h = e >> 9, d = e & (D_ - 1);          // e = h*512 + d
        g_W1T[e] = W1[d * H_ + h];
    }
    if (blockIdx.x == 0) {                          // bc[j] = W2[j,:]·b1 + b2[j]
        float s = 0.f;
        const float* w2row = W2 + (size_t)tid * D_;
        for (int d = 0; d < D_; d += 4) {
            float4 w  = *(const float4*)(w2row + d);
            float4 bb = *(const float4*)(b1 + d);
            s += w.x * bb.x + w.y * bb.y + w.z * bb.z + w.w * bb.w;
        }
        g_bc[tid] = s + b2[tid];
    }
    gbar(bar);

    // ---- P1/P2: Wc = W2 @ W1  (as A=W2[256x512], W=W1T[256x512], K=512) ----
    gemm64(W2, D_, g_W1T, D_, g_part, H_, B_ * H_, 4, 4, 8, 64, sA, sW);
    gbar(bar);
    for (int e = gtid; e < H_ * H_; e += GSTR) {
        float s = 0.f;
        #pragma unroll
        for (int k = 0; k < 8; k++) s += __ldcg(g_part + (size_t)k * (B_ * H_) + e);
        g_Wc[e] = s;
    }
    gbar(bar);

    // ---- time loop ----
    float tprev = 0.f;
    for (int t = 0; t < T_; t++) {
        float tcur  = batch[2 * t];                 // times shared across batch
        float dt    = tcur - tprev;
        tprev = tcur;
        float hstep = dt * (1.f / SSUB);

        for (int s = 0; s < SSUB; s++) {
            for (int i = 0; i < 4; i++) {
                // one RK4 stage: dot = u @ Wc^T   (partials, ksplit 8)
                gemm64(g_u, H_, g_Wc, H_, g_part, H_, B_ * H_, 4, 4, 8, 32, sA, sW);
                gbar(bar);
                // fused elementwise: k = tanh(dot + bc), RK4 bookkeeping
                for (int e = gtid; e < B_ * H_; e += GSTR) {
                    float dot = 0.f;
                    #pragma unroll
                    for (int kk = 0; kk < 8; kk++)
                        dot += __ldcg(g_part + (size_t)kk * (B_ * H_) + e);
                    float kv = tanhf(dot + __ldcg(g_bc + (e & (H_ - 1))));
                    float yv = __ldcg(g_y + e);
                    if (i == 0) {
                        g_acc[e] = kv;
                        g_u[e]   = yv + 0.5f * hstep * kv;
                    } else if (i == 1) {
                        g_acc[e] = __ldcg(g_acc + e) + 2.f * kv;
                        g_u[e]   = yv + 0.5f * hstep * kv;
                    } else if (i == 2) {
                        g_acc[e] = __ldcg(g_acc + e) + 2.f * kv;
                        g_u[e]   = yv + hstep * kv;
                    } else {
                        float yn = yv + (hstep * (1.f / 6.f)) * (__ldcg(g_acc + e) + kv);
                        g_y[e] = yn;
                        g_u[e] = yn;
                    }
                }
                gbar(bar);
            }
        }

        // ---- GRU: gh = y @ W_hh^T (partials, ksplit 2), then gates ----
        gemm64(g_y, H_, W_hh, H_, g_partG, N3_, B_ * N3_, 4, 12, 2, 128, sA, sW);
        gbar(bar);
        for (int e = gtid; e < B_ * H_; e += GSTR) {
            int b = e >> 8, j = e & (H_ - 1);
            const float* p0 = g_partG + (size_t)b * N3_ + j;
            float ghr = __ldcg(p0)       + __ldcg(p0 + B_ * N3_)       + b_hh[j];
            float ghz = __ldcg(p0 + 256) + __ldcg(p0 + B_ * N3_ + 256) + b_hh[j + 256];
            float ghn = __ldcg(p0 + 512) + __ldcg(p0 + B_ * N3_ + 512) + b_hh[j + 512];
            float x  = batch[(b * T_ + t) * 2 + 1];
            float gr = x * W_ih[j]       + b_ih[j];
            float gz = x * W_ih[j + 256] + b_ih[j + 256];
            float gn = x * W_ih[j + 512] + b_ih[j + 512];
            float r  = sigm(gr + ghr);
            float z  = sigm(gz + ghz);
            float n  = tanhf(gn + r * ghn);
            float hp = __ldcg(g_y + e);
            float ht = (1.f - z) * n + z * hp;
            float m  = mask[b * T_ + t];
            float hn2 = m * ht + (1.f - m) * hp;
            g_y[e] = hn2;
            g_u[e] = hn2;
            if (t == T_ - 1) out[e] = hn2;
        }
        gbar(bar);
    }
}

extern "C" void kernel_launch(void* const* d_in, const int* in_sizes, int n_in,
                              void* d_out, int out_size) {
    const float* batch = (const float*)d_in[0];
    const float* mask  = (const float*)d_in[1];
    const float* W1    = (const float*)d_in[2];
    const float* b1    = (const float*)d_in[3];
    const float* W2    = (const float*)d_in[4];
    const float* b2    = (const float*)d_in[5];
    const float* W_ih  = (const float*)d_in[6];
    const float* b_ih  = (const float*)d_in[7];
    const float* W_hh  = (const float*)d_in[8];
    const float* b_hh  = (const float*)d_in[9];
    float* out = (float*)d_out;

    ode_rnn_kernel<<<NCTA, NTHR>>>(batch, mask, W1, b1, W2, b2,
                                   W_ih, b_ih, W_hh, b_hh, out);
}

// round 3
// speedup vs baseline: 3.5677x; 3.5677x over previous
#include <cuda_runtime.h>
#include <math.h>

#define B_   256
#define T_   64
#define H_   256
#define D_   512
#define NCTA 128
#define NTHR 256

#define PAD  260                       // smem row stride (floats), conflict-free
#define SA_OFF   0
#define SWC_OFF  (16 * PAD)            // 4160
#define SWH_OFF  (SWC_OFF + 32 * PAD)  // 12480
#define SMEM_FLOATS (SWH_OFF + 3 * 32 * PAD)   // 37440 floats = 149760 B

// ---------------- device scratch (no allocations allowed) -------------------
__device__ __align__(16) float g_u [B_ * H_];   // shared state (h / RK stage input)
__device__ __align__(16) float g_Wc[H_ * H_];   // fused ODE weight W2@W1
__device__ __align__(16) float g_bc[H_];        // fused ODE bias
__device__ unsigned g_arrive  = 0;
__device__ unsigned g_release = 0;

// ---------------- grid barrier (replay-safe: monotone release) --------------
__device__ __forceinline__ void gbar(unsigned &next) {
    __threadfence();
    __syncthreads();
    if (threadIdx.x == 0) {
        unsigned tgt = next;
        if (atomicAdd(&g_arrive, 1u) == NCTA - 1) {
            g_arrive = 0;
            __threadfence();
            *(volatile unsigned*)&g_release = tgt;
        } else {
            while ((int)(*(volatile unsigned*)&g_release - tgt) < 0) { }
        }
        __threadfence();
    }
    __syncthreads();
    next++;
}

__device__ __forceinline__ float sigm(float x) { return 1.f / (1.f + expf(-x)); }

// ---------------- persistent kernel ------------------------------------------
__global__ void __launch_bounds__(NTHR, 1)
ode_rnn_kernel(const float* __restrict__ batch, const float* __restrict__ mask,
               const float* __restrict__ W1,   const float* __restrict__ b1,
               const float* __restrict__ W2,   const float* __restrict__ b2,
               const float* __restrict__ W_ih, const float* __restrict__ b_ih,
               const float* __restrict__ W_hh, const float* __restrict__ b_hh,
               float* __restrict__ out)
{
    extern __shared__ float sm[];
    float* sA  = sm + SA_OFF;    // [16][PAD]  A tile (u rows)
    float* sWc = sm + SWC_OFF;   // [32][PAD]  persistent Wc rows n0..n0+31
    float* sWh = sm + SWH_OFF;   // [3][32][PAD] persistent W_hh gate tiles

    const int tid = threadIdx.x;
    const int mt  = blockIdx.x >> 3;       // 0..15  (batch-row tile)
    const int nt  = blockIdx.x & 7;        // 0..7   (feature-col tile)
    const int m0  = mt << 4;               // 16 rows
    const int n0  = nt << 5;               // 32 cols
    const int w   = tid >> 5;              // warp id 0..7 -> rows w, w+8
    const int c   = tid & 31;              // lane -> column

    __shared__ unsigned s_base;
    if (tid == 0) s_base = *(volatile unsigned*)&g_release;
    __syncthreads();
    unsigned bar = s_base + 1;

    // ================= setup =================
    // init u = h0 = 0
    for (int e = blockIdx.x * NTHR + tid; e < B_ * H_; e += NCTA * NTHR)
        g_u[e] = 0.f;

    // Wc rows: CTA computes rows j0, j0+1 (Wc[j][h] = sum_d W2[j][d] * W1[d][h])
    {
        const int j0 = blockIdx.x * 2;
        const int h  = tid;
        const float* w2a = W2 + (size_t)j0 * D_;
        const float* w2b = w2a + D_;
        float a0 = 0.f, a1 = 0.f;
        #pragma unroll 8
        for (int d = 0; d < D_; d++) {
            float w1v = __ldg(&W1[d * H_ + h]);        // coalesced
            a0 += __ldg(&w2a[d]) * w1v;                // broadcast
            a1 += __ldg(&w2b[d]) * w1v;
        }
        g_Wc[(size_t)j0 * H_ + h]       = a0;
        g_Wc[(size_t)(j0 + 1) * H_ + h] = a1;
    }
    // bc on CTA0: bc[j] = W2[j,:]·b1 + b2[j]
    if (blockIdx.x == 0) {
        const int j = tid;
        const float* w2r = W2 + (size_t)j * D_;
        float s = 0.f;
        #pragma unroll 8
        for (int d = 0; d < D_; d++) s += __ldg(&w2r[d]) * __ldg(&b1[d]);
        g_bc[j] = s + __ldg(&b2[j]);
    }
    gbar(bar);

    // load persistent B tiles into smem
    for (int idx = tid; idx < 32 * 64; idx += NTHR) {           // Wc tile
        int r = idx >> 6, q = (idx & 63) << 2;
        float4 v = __ldcg((const float4*)&g_Wc[(size_t)(n0 + r) * H_ + q]);
        *(float4*)&sWc[r * PAD + q] = v;
    }
    for (int idx = tid; idx < 3 * 32 * 64; idx += NTHR) {       // W_hh gate tiles
        int g = idx >> 11;               // gate 0..2
        int r = (idx >> 6) & 31;
        int q = (idx & 63) << 2;
        float4 v = __ldg((const float4*)&W_hh[(size_t)(g * H_ + n0 + r) * H_ + q]);
        *(float4*)&sWh[(g * 32 + r) * PAD + q] = v;
    }
    // per-thread constants (column j = n0 + c is fixed forever)
    const int j   = n0 + c;
    const float c_bc  = *(volatile float*)&g_bc[j];   // bypass L1 (written pre-barrier)
    const float c_bhr = __ldg(&b_hh[j]);
    const float c_bhz = __ldg(&b_hh[j + 256]);
    const float c_bhn = __ldg(&b_hh[j + 512]);
    const float c_wir = __ldg(&W_ih[j]);
    const float c_wiz = __ldg(&W_ih[j + 256]);
    const float c_win = __ldg(&W_ih[j + 512]);
    const float c_bir = __ldg(&b_ih[j]);
    const float c_biz = __ldg(&b_ih[j + 256]);
    const float c_bin = __ldg(&b_ih[j + 512]);
    __syncthreads();

    const int b1r = m0 + w;         // first owned batch row
    const int b2r = m0 + w + 8;     // second owned batch row
    const int e1  = b1r * H_ + j;
    const int e2  = b2r * H_ + j;
    const float* pa1 = sA + w * PAD;
    const float* pa2 = sA + (w + 8) * PAD;
    const float* pbc = sWc + c * PAD;
    const float* pbr = sWh + (0 * 32 + c) * PAD;
    const float* pbz = sWh + (1 * 32 + c) * PAD;
    const float* pbn = sWh + (2 * 32 + c) * PAD;

    float ry1 = 0.f, ry2 = 0.f;         // RK4 base state (registers)
    float rk1 = 0.f, rk2 = 0.f;         // RK4 accumulator (registers)

    // ================= time loop =================
    float tprev = 0.f;
    for (int t = 0; t < T_; t++) {
        const float tcur = __ldg(&batch[2 * t]);
        const float dt   = tcur - tprev;
        tprev = tcur;
        const int   nsub  = (dt > 0.1f) ? 2 : 1;
        const float hstep = dt / (float)nsub;

        for (int s = 0; s < nsub; s++) {
            #pragma unroll
            for (int i = 0; i < 4; i++) {
                // ---- load A tile (u rows m0..m0+15) ----
                #pragma unroll
                for (int rpt = 0; rpt < 4; rpt++) {
                    int idx = tid + rpt * NTHR;         // 0..1023
                    int r = idx >> 6, q = (idx & 63) << 2;
                    float4 v = __ldcg((const float4*)&g_u[(size_t)(m0 + r) * H_ + q]);
                    *(float4*)&sA[r * PAD + q] = v;
                }
                __syncthreads();
                // ---- GEMM: 2 dots of K=256 ----
                float acc1 = 0.f, acc2 = 0.f;
                #pragma unroll 16
                for (int k = 0; k < H_; k += 4) {
                    float4 b  = *(const float4*)(pbc + k);
                    float4 a1 = *(const float4*)(pa1 + k);
                    float4 a2 = *(const float4*)(pa2 + k);
                    acc1 += a1.x * b.x; acc1 += a1.y * b.y;
                    acc1 += a1.z * b.z; acc1 += a1.w * b.w;
                    acc2 += a2.x * b.x; acc2 += a2.y * b.y;
                    acc2 += a2.z * b.z; acc2 += a2.w * b.w;
                }
                // ---- fused RK4 epilogue (state in registers) ----
                float kv1 = tanhf(acc1 + c_bc);
                float kv2 = tanhf(acc2 + c_bc);
                float u1, u2;
                if (i == 0) {
                    rk1 = kv1;              rk2 = kv2;
                    u1 = ry1 + 0.5f * hstep * kv1;  u2 = ry2 + 0.5f * hstep * kv2;
                } else if (i == 1) {
                    rk1 += 2.f * kv1;       rk2 += 2.f * kv2;
                    u1 = ry1 + 0.5f * hstep * kv1;  u2 = ry2 + 0.5f * hstep * kv2;
                } else if (i == 2) {
                    rk1 += 2.f * kv1;       rk2 += 2.f * kv2;
                    u1 = ry1 + hstep * kv1;         u2 = ry2 + hstep * kv2;
                } else {
                    u1 = ry1 + (hstep * (1.f / 6.f)) * (rk1 + kv1);
                    u2 = ry2 + (hstep * (1.f / 6.f)) * (rk2 + kv2);
                    ry1 = u1; ry2 = u2;
                }
                g_u[e1] = u1;   // coalesced 128B per warp
                g_u[e2] = u2;
                __syncthreads();     // all reads of sA done before next overwrite
                gbar(bar);
            }
        }

        // ---- GRU step: gh = h @ W_hh^T (3 gate tiles), fused gates ----
        #pragma unroll
        for (int rpt = 0; rpt < 4; rpt++) {
            int idx = tid + rpt * NTHR;
            int r = idx >> 6, q = (idx & 63) << 2;
            float4 v = __ldcg((const float4*)&g_u[(size_t)(m0 + r) * H_ + q]);
            *(float4*)&sA[r * PAD + q] = v;
        }
        __syncthreads();
        float ar1 = 0.f, az1 = 0.f, an1 = 0.f;
        float ar2 = 0.f, az2 = 0.f, an2 = 0.f;
        #pragma unroll 8
        for (int k = 0; k < H_; k += 4) {
            float4 a1 = *(const float4*)(pa1 + k);
            float4 a2 = *(const float4*)(pa2 + k);
            float4 br = *(const float4*)(pbr + k);
            float4 bz = *(const float4*)(pbz + k);
            float4 bn = *(const float4*)(pbn + k);
            ar1 += a1.x*br.x + a1.y*br.y + a1.z*br.z + a1.w*br.w;
            az1 += a1.x*bz.x + a1.y*bz.y + a1.z*bz.z + a1.w*bz.w;
            an1 += a1.x*bn.x + a1.y*bn.y + a1.z*bn.z + a1.w*bn.w;
            ar2 += a2.x*br.x + a2.y*br.y + a2.z*br.z + a2.w*br.w;
            az2 += a2.x*bz.x + a2.y*bz.y + a2.z*bz.z + a2.w*bz.w;
            an2 += a2.x*bn.x + a2.y*bn.y + a2.z*bn.z + a2.w*bn.w;
        }
        {
            float x1 = __ldg(&batch[(b1r * T_ + t) * 2 + 1]);
            float m1 = __ldg(&mask[b1r * T_ + t]);
            float r_ = sigm(x1 * c_wir + c_bir + ar1 + c_bhr);
            float z_ = sigm(x1 * c_wiz + c_biz + az1 + c_bhz);
            float n_ = tanhf(x1 * c_win + c_bin + r_ * (an1 + c_bhn));
            float ht = (1.f - z_) * n_ + z_ * ry1;
            ry1 = m1 * ht + (1.f - m1) * ry1;
            g_u[e1] = ry1;
            if (t == T_ - 1) out[e1] = ry1;
        }
        {
            float x2 = __ldg(&batch[(b2r * T_ + t) * 2 + 1]);
            float m2 = __ldg(&mask[b2r * T_ + t]);
            float r_ = sigm(x2 * c_wir + c_bir + ar2 + c_bhr);
            float z_ = sigm(x2 * c_wiz + c_biz + az2 + c_bhz);
            float n_ = tanhf(x2 * c_win + c_bin + r_ * (an2 + c_bhn));
            float ht = (1.f - z_) * n_ + z_ * ry2;
            ry2 = m2 * ht + (1.f - m2) * ry2;
            g_u[e2] = ry2;
            if (t == T_ - 1) out[e2] = ry2;
        }
        __syncthreads();
        gbar(bar);
    }
}

extern "C" void kernel_launch(void* const* d_in, const int* in_sizes, int n_in,
                              void* d_out, int out_size) {
    const float* batch = (const float*)d_in[0];
    const float* mask  = (const float*)d_in[1];
    const float* W1    = (const float*)d_in[2];
    const float* b1    = (const float*)d_in[3];
    const float* W2    = (const float*)d_in[4];
    const float* b2    = (const float*)d_in[5];
    const float* W_ih  = (const float*)d_in[6];
    const float* b_ih  = (const float*)d_in[7];
    const float* W_hh  = (const float*)d_in[8];
    const float* b_hh  = (const float*)d_in[9];
    float* out = (float*)d_out;

    static bool attr_set = false;
    cudaFuncSetAttribute(ode_rnn_kernel,
                         cudaFuncAttributeMaxDynamicSharedMemorySize,
                         SMEM_FLOATS * sizeof(float));
    (void)attr_set;

    ode_rnn_kernel<<<NCTA, NTHR, SMEM_FLOATS * sizeof(float)>>>(
        batch, mask, W1, b1, W2, b2, W_ih, b_ih, W_hh, b_hh, out);
}